// round 1
// baseline (speedup 1.0000x reference)
#include <cuda_runtime.h>
#include <math.h>

#define NN 50000
#define EE 800000
#define HH 128
#define FIN 64
#define CC 16
#define LL 3

// ---------------- scratch (static device globals; no allocation) ----------------
__device__ float g_h[NN * HH];        // hidden state  [N,128]
__device__ float g_m[NN * HH];        // messages      [N,128]
__device__ float g_agg[NN * HH];      // aggregated    [N,128]
__device__ float g_gi[NN * 3 * HH];   // input gates   [N,384]
__device__ float g_gh[NN * 3 * HH];   // hidden gates  [N,384]
__device__ int   g_edge[2 * EE];      // normalized int32 edge index
__device__ int   g_deg[NN];
__device__ int   g_rowptr[NN + 1];
__device__ int   g_cursor[NN];
__device__ int   g_col[EE];
__device__ int   g_is64;

// ---------------- edge dtype probe + normalize ----------------
__global__ void k_detect(const void* ei) {
    if (blockIdx.x == 0 && threadIdx.x == 0) {
        const long long* p64 = (const long long*)ei;
        int ok64 = 1;
        for (int i = 0; i < 64; ++i) {
            long long v = p64[i];
            if (v < 0 || v >= NN) { ok64 = 0; break; }
        }
        g_is64 = ok64;
    }
}

__global__ void k_convert(const void* ei) {
    int e = blockIdx.x * blockDim.x + threadIdx.x;
    if (e < 2 * EE) {
        int v;
        if (g_is64) v = (int)((const long long*)ei)[e];
        else        v = ((const int*)ei)[e];
        g_edge[e] = v;
    }
}

// ---------------- init: h = pad(x) ----------------
__global__ void k_pad(const float* __restrict__ x) {
    int i = blockIdx.x * blockDim.x + threadIdx.x;
    if (i < NN * HH) {
        int n = i >> 7, k = i & 127;
        g_h[i] = (k < FIN) ? x[n * FIN + k] : 0.f;
    }
}

// ---------------- CSR build ----------------
__global__ void k_zero_deg() {
    int i = blockIdx.x * blockDim.x + threadIdx.x;
    if (i < NN) g_deg[i] = 0;
}

__global__ void k_hist() {
    int e = blockIdx.x * blockDim.x + threadIdx.x;
    if (e < EE) atomicAdd(&g_deg[g_edge[EE + e]], 1);
}

// single-block chunked Hillis-Steele exclusive scan over g_deg -> g_rowptr
__global__ void k_scan() {
    __shared__ int s[1024];
    int t = threadIdx.x;
    int carry = 0;
    for (int c0 = 0; c0 < NN; c0 += 1024) {
        int idx = c0 + t;
        int v = (idx < NN) ? g_deg[idx] : 0;
        s[t] = v;
        __syncthreads();
        for (int off = 1; off < 1024; off <<= 1) {
            int add = (t >= off) ? s[t - off] : 0;
            __syncthreads();
            s[t] += add;
            __syncthreads();
        }
        if (idx < NN) g_rowptr[idx] = carry + s[t] - v;  // exclusive
        int tot = s[1023];
        __syncthreads();
        carry += tot;
    }
    if (t == 0) g_rowptr[NN] = carry;
}

__global__ void k_cursor() {
    int i = blockIdx.x * blockDim.x + threadIdx.x;
    if (i < NN) g_cursor[i] = g_rowptr[i];
}

__global__ void k_fill() {
    int e = blockIdx.x * blockDim.x + threadIdx.x;
    if (e < EE) {
        int d = g_edge[EE + e];
        int srcn = g_edge[e];
        int pos = atomicAdd(&g_cursor[d], 1);
        g_col[pos] = srcn;
    }
}

// ---------------- aggregation: agg[n,:] = sum over in-edges of m[src,:] ----------------
__global__ void k_gather() {
    int n = blockIdx.x;
    int t = threadIdx.x;  // 128 threads = one feature each
    int beg = g_rowptr[n], end = g_rowptr[n + 1];
    float acc = 0.f;
    int e = beg;
    for (; e + 4 <= end; e += 4) {
        int s0 = g_col[e], s1 = g_col[e + 1], s2 = g_col[e + 2], s3 = g_col[e + 3];
        acc += g_m[s0 * HH + t];
        acc += g_m[s1 * HH + t];
        acc += g_m[s2 * HH + t];
        acc += g_m[s3 * HH + t];
    }
    for (; e < end; ++e) acc += g_m[g_col[e] * HH + t];
    g_agg[n * HH + t] = acc;
}

// ---------------- SGEMM: m = h @ W  (W row-major [k][p], K=P=128) ----------------
// BM=BN=128, BK=32, 256 threads, 8x8 per thread
__global__ __launch_bounds__(256, 2) void k_gemm_m(const float* __restrict__ Wt) {
    __shared__ float As[32 * 128];
    __shared__ float Bs[32 * 128];
    int t = threadIdx.x;
    int tx = t & 15, ty = t >> 4;
    int row0 = blockIdx.x * 128;
    float acc[8][8];
#pragma unroll
    for (int i = 0; i < 8; ++i)
#pragma unroll
        for (int j = 0; j < 8; ++j) acc[i][j] = 0.f;

    for (int k0 = 0; k0 < 128; k0 += 32) {
#pragma unroll
        for (int q = 0; q < 4; ++q) {
            int idx = q * 256 + t;
            int m = idx >> 3, kq = idx & 7;
            int row = row0 + m;
            float4 v = make_float4(0.f, 0.f, 0.f, 0.f);
            if (row < NN) v = *(const float4*)&g_h[row * 128 + k0 + kq * 4];
            As[(kq * 4 + 0) * 128 + m] = v.x;
            As[(kq * 4 + 1) * 128 + m] = v.y;
            As[(kq * 4 + 2) * 128 + m] = v.z;
            As[(kq * 4 + 3) * 128 + m] = v.w;
        }
#pragma unroll
        for (int q = 0; q < 4; ++q) {
            int idx = q * 256 + t;
            int k = idx >> 5, pq = idx & 31;
            *(float4*)&Bs[k * 128 + pq * 4] =
                *(const float4*)&Wt[(k0 + k) * 128 + pq * 4];
        }
        __syncthreads();
#pragma unroll
        for (int kk = 0; kk < 32; ++kk) {
            float4 a0 = *(float4*)&As[kk * 128 + ty * 8];
            float4 a1 = *(float4*)&As[kk * 128 + ty * 8 + 4];
            float4 b0 = *(float4*)&Bs[kk * 128 + tx * 8];
            float4 b1 = *(float4*)&Bs[kk * 128 + tx * 8 + 4];
            float a[8] = {a0.x, a0.y, a0.z, a0.w, a1.x, a1.y, a1.z, a1.w};
            float b[8] = {b0.x, b0.y, b0.z, b0.w, b1.x, b1.y, b1.z, b1.w};
#pragma unroll
            for (int i = 0; i < 8; ++i)
#pragma unroll
                for (int j = 0; j < 8; ++j) acc[i][j] += a[i] * b[j];
        }
        __syncthreads();
    }
#pragma unroll
    for (int i = 0; i < 8; ++i) {
        int row = row0 + ty * 8 + i;
        if (row < NN) {
            float4 o0 = make_float4(acc[i][0], acc[i][1], acc[i][2], acc[i][3]);
            float4 o1 = make_float4(acc[i][4], acc[i][5], acc[i][6], acc[i][7]);
            *(float4*)&g_m[row * 128 + tx * 8] = o0;
            *(float4*)&g_m[row * 128 + tx * 8 + 4] = o1;
        }
    }
}

// ---------------- SGEMM: C[N,384] = A[N,128] @ B[384,128]^T + bias ----------------
// sel=0: A=g_agg -> C=g_gi ; sel=1: A=g_h -> C=g_gh
__global__ __launch_bounds__(256, 2) void k_gemm_bt(int sel,
                                                    const float* __restrict__ B,
                                                    const float* __restrict__ bias) {
    const float* A = sel ? g_h : g_agg;
    float*       C = sel ? g_gh : g_gi;
    __shared__ float As[32 * 128];
    __shared__ float Bs[32 * 128];
    int t = threadIdx.x;
    int tx = t & 15, ty = t >> 4;
    int row0 = blockIdx.x * 128;
    int p0 = blockIdx.y * 128;
    float acc[8][8];
#pragma unroll
    for (int i = 0; i < 8; ++i)
#pragma unroll
        for (int j = 0; j < 8; ++j) acc[i][j] = 0.f;

    for (int k0 = 0; k0 < 128; k0 += 32) {
#pragma unroll
        for (int q = 0; q < 4; ++q) {
            int idx = q * 256 + t;
            int m = idx >> 3, kq = idx & 7;
            int row = row0 + m;
            float4 v = make_float4(0.f, 0.f, 0.f, 0.f);
            if (row < NN) v = *(const float4*)&A[row * 128 + k0 + kq * 4];
            As[(kq * 4 + 0) * 128 + m] = v.x;
            As[(kq * 4 + 1) * 128 + m] = v.y;
            As[(kq * 4 + 2) * 128 + m] = v.z;
            As[(kq * 4 + 3) * 128 + m] = v.w;
        }
#pragma unroll
        for (int q = 0; q < 4; ++q) {
            int idx = q * 256 + t;
            int p = idx >> 3, kq = idx & 7;
            float4 v = *(const float4*)&B[(p0 + p) * 128 + k0 + kq * 4];
            Bs[(kq * 4 + 0) * 128 + p] = v.x;
            Bs[(kq * 4 + 1) * 128 + p] = v.y;
            Bs[(kq * 4 + 2) * 128 + p] = v.z;
            Bs[(kq * 4 + 3) * 128 + p] = v.w;
        }
        __syncthreads();
#pragma unroll
        for (int kk = 0; kk < 32; ++kk) {
            float4 a0 = *(float4*)&As[kk * 128 + ty * 8];
            float4 a1 = *(float4*)&As[kk * 128 + ty * 8 + 4];
            float4 b0 = *(float4*)&Bs[kk * 128 + tx * 8];
            float4 b1 = *(float4*)&Bs[kk * 128 + tx * 8 + 4];
            float a[8] = {a0.x, a0.y, a0.z, a0.w, a1.x, a1.y, a1.z, a1.w};
            float b[8] = {b0.x, b0.y, b0.z, b0.w, b1.x, b1.y, b1.z, b1.w};
#pragma unroll
            for (int i = 0; i < 8; ++i)
#pragma unroll
                for (int j = 0; j < 8; ++j) acc[i][j] += a[i] * b[j];
        }
        __syncthreads();
    }
    float bj[8];
#pragma unroll
    for (int j = 0; j < 8; ++j) bj[j] = bias[p0 + tx * 8 + j];
#pragma unroll
    for (int i = 0; i < 8; ++i) {
        int row = row0 + ty * 8 + i;
        if (row < NN) {
            float4 o0 = make_float4(acc[i][0] + bj[0], acc[i][1] + bj[1],
                                    acc[i][2] + bj[2], acc[i][3] + bj[3]);
            float4 o1 = make_float4(acc[i][4] + bj[4], acc[i][5] + bj[5],
                                    acc[i][6] + bj[6], acc[i][7] + bj[7]);
            *(float4*)&C[row * 384 + p0 + tx * 8] = o0;
            *(float4*)&C[row * 384 + p0 + tx * 8 + 4] = o1;
        }
    }
}

// ---------------- GRU gates (torch order r, z, n) ----------------
__global__ void k_gru() {
    int i = blockIdx.x * blockDim.x + threadIdx.x;
    if (i >= NN * HH) return;
    int n = i >> 7, j = i & 127;
    const float* gi = g_gi + n * 384;
    const float* gh = g_gh + n * 384;
    float r = 1.f / (1.f + expf(-(gi[j] + gh[j])));
    float z = 1.f / (1.f + expf(-(gi[128 + j] + gh[128 + j])));
    float nn = tanhf(gi[256 + j] + r * gh[256 + j]);
    float h = g_h[i];
    g_h[i] = (1.f - z) * nn + z * h;
}

// ---------------- classifier + log_softmax (one warp per row) ----------------
__global__ void k_cls(const float* __restrict__ lw, const float* __restrict__ lb,
                      float* __restrict__ out) {
    int gt = blockIdx.x * blockDim.x + threadIdx.x;
    int row = gt >> 5;
    int lane = gt & 31;
    if (row >= NN) return;
    const float* hrow = g_h + row * 128;
    float acc[CC];
#pragma unroll
    for (int c = 0; c < CC; ++c) acc[c] = 0.f;
#pragma unroll
    for (int kq = 0; kq < 4; ++kq) {
        int k = lane + kq * 32;
        float hv = hrow[k];
#pragma unroll
        for (int c = 0; c < CC; ++c) acc[c] += hv * lw[c * 128 + k];
    }
#pragma unroll
    for (int c = 0; c < CC; ++c) {
#pragma unroll
        for (int off = 16; off; off >>= 1)
            acc[c] += __shfl_xor_sync(0xffffffffu, acc[c], off);
        acc[c] += lb[c];
    }
    float mx = acc[0];
#pragma unroll
    for (int c = 1; c < CC; ++c) mx = fmaxf(mx, acc[c]);
    float se = 0.f;
#pragma unroll
    for (int c = 0; c < CC; ++c) se += expf(acc[c] - mx);
    float lse = mx + logf(se);
    if (lane < CC) out[row * CC + lane] = acc[lane] - lse;
}

// ---------------- launch ----------------
extern "C" void kernel_launch(void* const* d_in, const int* in_sizes, int n_in,
                              void* d_out, int out_size) {
    const float* x     = (const float*)d_in[0];
    const void*  ei    = d_in[1];
    const float* W     = (const float*)d_in[2];
    const float* w_ih  = (const float*)d_in[3];
    const float* w_hh  = (const float*)d_in[4];
    const float* b_ih  = (const float*)d_in[5];
    const float* b_hh  = (const float*)d_in[6];
    const float* lw    = (const float*)d_in[7];
    const float* lb    = (const float*)d_in[8];
    float* out = (float*)d_out;

    // normalize edge index dtype (int64 vs int32) and build CSR once
    k_detect<<<1, 32>>>(ei);
    k_convert<<<(2 * EE + 255) / 256, 256>>>(ei);
    k_pad<<<(NN * HH + 255) / 256, 256>>>(x);
    k_zero_deg<<<(NN + 255) / 256, 256>>>();
    k_hist<<<(EE + 255) / 256, 256>>>();
    k_scan<<<1, 1024>>>();
    k_cursor<<<(NN + 255) / 256, 256>>>();
    k_fill<<<(EE + 255) / 256, 256>>>();

    dim3 gm((NN + 127) / 128, 1);
    dim3 gg((NN + 127) / 128, 3);
    for (int l = 0; l < LL; ++l) {
        k_gemm_m<<<gm, 256>>>(W + l * HH * HH);
        k_gather<<<NN, 128>>>();
        k_gemm_bt<<<gg, 256>>>(0, w_ih, b_ih);   // gi = agg @ w_ih^T + b_ih
        k_gemm_bt<<<gg, 256>>>(1, w_hh, b_hh);   // gh = h   @ w_hh^T + b_hh
        k_gru<<<(NN * HH + 255) / 256, 256>>>();
    }
    k_cls<<<(NN * 32 + 255) / 256, 256>>>(lw, lb, out);
}

// round 2
// speedup vs baseline: 1.5782x; 1.5782x over previous
#include <cuda_runtime.h>
#include <math.h>

#define NN 50000
#define EE 800000
#define HH 128
#define FIN 64
#define CC 16
#define LL 3

// ---------------- scratch (static device globals; no allocation) ----------------
__device__ float g_h[NN * HH];        // hidden state  [N,128]
__device__ float g_m[NN * HH];        // messages      [N,128]
__device__ float g_agg[NN * HH];      // aggregated    [N,128]
__device__ float g_gi[NN * 3 * HH];   // input gates   [N,384]
__device__ float g_gh[NN * 3 * HH];   // hidden gates  [N,384]
__device__ float g_Wt[LL * HH * HH];  // transposed per-layer W: [l][p][k]
__device__ int   g_edge[2 * EE];      // normalized int32 edge index
__device__ int   g_deg[NN];
__device__ int   g_rowptr[NN + 1];
__device__ int   g_cursor[NN];
__device__ int   g_col[EE];
__device__ int   g_is64;

// ---------------- edge dtype probe + normalize ----------------
__global__ void k_detect(const void* ei) {
    if (blockIdx.x == 0 && threadIdx.x == 0) {
        const long long* p64 = (const long long*)ei;
        int ok64 = 1;
        for (int i = 0; i < 64; ++i) {
            long long v = p64[i];
            if (v < 0 || v >= NN) { ok64 = 0; break; }
        }
        g_is64 = ok64;
    }
}

__global__ void k_convert(const void* ei) {
    int e = blockIdx.x * blockDim.x + threadIdx.x;
    if (e < 2 * EE) {
        int v;
        if (g_is64) v = (int)((const long long*)ei)[e];
        else        v = ((const int*)ei)[e];
        g_edge[e] = v;
    }
}

// ---------------- init: h = pad(x), Wt = W^T per layer ----------------
__global__ void k_pad(const float* __restrict__ x) {
    int i = blockIdx.x * blockDim.x + threadIdx.x;
    if (i < NN * HH) {
        int n = i >> 7, k = i & 127;
        g_h[i] = (k < FIN) ? x[n * FIN + k] : 0.f;
    }
}

__global__ void k_transW(const float* __restrict__ W) {
    int i = blockIdx.x * blockDim.x + threadIdx.x;
    if (i < LL * HH * HH) {
        int l = i >> 14;
        int k = (i >> 7) & 127;
        int p = i & 127;
        g_Wt[(l << 14) + p * 128 + k] = W[i];   // Wt[l][p][k] = W[l][k][p]
    }
}

// ---------------- CSR build ----------------
__global__ void k_zero_deg() {
    int i = blockIdx.x * blockDim.x + threadIdx.x;
    if (i < NN) g_deg[i] = 0;
}

__global__ void k_hist() {
    int e = blockIdx.x * blockDim.x + threadIdx.x;
    if (e < EE) atomicAdd(&g_deg[g_edge[EE + e]], 1);
}

__global__ void k_scan() {
    __shared__ int s[1024];
    int t = threadIdx.x;
    int carry = 0;
    for (int c0 = 0; c0 < NN; c0 += 1024) {
        int idx = c0 + t;
        int v = (idx < NN) ? g_deg[idx] : 0;
        s[t] = v;
        __syncthreads();
        for (int off = 1; off < 1024; off <<= 1) {
            int add = (t >= off) ? s[t - off] : 0;
            __syncthreads();
            s[t] += add;
            __syncthreads();
        }
        if (idx < NN) g_rowptr[idx] = carry + s[t] - v;
        int tot = s[1023];
        __syncthreads();
        carry += tot;
    }
    if (t == 0) g_rowptr[NN] = carry;
}

__global__ void k_cursor() {
    int i = blockIdx.x * blockDim.x + threadIdx.x;
    if (i < NN) g_cursor[i] = g_rowptr[i];
}

__global__ void k_fill() {
    int e = blockIdx.x * blockDim.x + threadIdx.x;
    if (e < EE) {
        int d = g_edge[EE + e];
        int srcn = g_edge[e];
        int pos = atomicAdd(&g_cursor[d], 1);
        g_col[pos] = srcn;
    }
}

// ---------------- aggregation ----------------
__global__ void k_gather() {
    int n = blockIdx.x;
    int t = threadIdx.x;
    int beg = g_rowptr[n], end = g_rowptr[n + 1];
    float acc = 0.f;
    int e = beg;
    for (; e + 4 <= end; e += 4) {
        int s0 = g_col[e], s1 = g_col[e + 1], s2 = g_col[e + 2], s3 = g_col[e + 3];
        acc += g_m[s0 * HH + t];
        acc += g_m[s1 * HH + t];
        acc += g_m[s2 * HH + t];
        acc += g_m[s3 * HH + t];
    }
    for (; e < end; ++e) acc += g_m[g_col[e] * HH + t];
    g_agg[n * HH + t] = acc;
}

// ---------------- tf32 tensor-core GEMM ----------------
// C[r, n0+col] = sum_k A[r][k] * Bt[n0+col][k]  (+ bias), K = 128.
// Block tile 128x128, 256 threads = 8 warps (2 m-warps x 4 n-warps),
// warp tile 64x32. Smem holds fragment-permuted tf32 chunks (BK=32).
__device__ __forceinline__ unsigned f2tf(float x) {
    unsigned r;
    asm("cvt.rna.tf32.f32 %0, %1;" : "=r"(r) : "f"(x));
    return r;
}

__global__ __launch_bounds__(256) void k_mma(const float* __restrict__ A,
                                             const float* __restrict__ Bt,
                                             const float* __restrict__ bias,
                                             float* __restrict__ C, int ldc) {
    __shared__ unsigned As[4096];   // [mf(8)][ks(4)][lane(32)][reg(4)]
    __shared__ unsigned Bs[4096];   // [nf(16)][ks(4)][lane(32)][reg(2)]
    int t = threadIdx.x;
    int lane = t & 31, w = t >> 5;
    int wm = w >> 2, wn = w & 3;
    int row0 = blockIdx.x * 128;
    int n0 = blockIdx.y * 128;

    float c[4][4][4];
#pragma unroll
    for (int i = 0; i < 4; ++i)
#pragma unroll
        for (int j = 0; j < 4; ++j)
#pragma unroll
            for (int r = 0; r < 4; ++r) c[i][j][r] = 0.f;

    for (int cc = 0; cc < 4; ++cc) {
        int k0 = cc * 32;
        // ---- stage A chunk (128 rows x 32 k) into fragment layout ----
#pragma unroll
        for (int q = 0; q < 2; ++q) {
            int idx = q * 256 + t;          // wait: need 4 iters for A
            (void)idx;
        }
#pragma unroll
        for (int q = 0; q < 4; ++q) {
            int idx = q * 256 + t;
            int m = idx >> 3, kq = idx & 7;
            int row = row0 + m;
            float4 v = make_float4(0.f, 0.f, 0.f, 0.f);
            if (row < NN) v = *(const float4*)&A[row * 128 + k0 + kq * 4];
            int mf = m >> 4, r16 = m & 15;
            int lanebase = (r16 & 7) * 4;
            int reghalf = r16 >> 3;
            int ks = kq >> 1, hi = kq & 1;
            int reg = hi * 2 + reghalf;
            unsigned* dst = &As[(mf * 4 + ks) * 128];
            dst[(lanebase + 0) * 4 + reg] = f2tf(v.x);
            dst[(lanebase + 1) * 4 + reg] = f2tf(v.y);
            dst[(lanebase + 2) * 4 + reg] = f2tf(v.z);
            dst[(lanebase + 3) * 4 + reg] = f2tf(v.w);
        }
        // ---- stage B chunk (128 n x 32 k) into fragment layout ----
#pragma unroll
        for (int q = 0; q < 4; ++q) {
            int idx = q * 256 + t;
            int n = idx >> 3, kq = idx & 7;
            float4 v = *(const float4*)&Bt[(n0 + n) * 128 + k0 + kq * 4];
            int nf = n >> 3, nl = n & 7;
            int ks = kq >> 1, hi = kq & 1;
            unsigned* dst = &Bs[(nf * 4 + ks) * 64];
            dst[(nl * 4 + 0) * 2 + hi] = f2tf(v.x);
            dst[(nl * 4 + 1) * 2 + hi] = f2tf(v.y);
            dst[(nl * 4 + 2) * 2 + hi] = f2tf(v.z);
            dst[(nl * 4 + 3) * 2 + hi] = f2tf(v.w);
        }
        __syncthreads();
        // ---- compute ----
#pragma unroll
        for (int ks = 0; ks < 4; ++ks) {
            uint4 a[4];
            uint2 b[4];
#pragma unroll
            for (int i = 0; i < 4; ++i)
                a[i] = *(const uint4*)&As[((wm * 4 + i) * 4 + ks) * 128 + lane * 4];
#pragma unroll
            for (int j = 0; j < 4; ++j)
                b[j] = *(const uint2*)&Bs[((wn * 4 + j) * 4 + ks) * 64 + lane * 2];
#pragma unroll
            for (int i = 0; i < 4; ++i)
#pragma unroll
                for (int j = 0; j < 4; ++j) {
                    asm volatile(
                        "mma.sync.aligned.m16n8k8.row.col.f32.tf32.tf32.f32 "
                        "{%0,%1,%2,%3}, {%4,%5,%6,%7}, {%8,%9}, {%0,%1,%2,%3};"
                        : "+f"(c[i][j][0]), "+f"(c[i][j][1]),
                          "+f"(c[i][j][2]), "+f"(c[i][j][3])
                        : "r"(a[i].x), "r"(a[i].y), "r"(a[i].z), "r"(a[i].w),
                          "r"(b[j].x), "r"(b[j].y));
                }
        }
        __syncthreads();
    }
    // ---- epilogue ----
#pragma unroll
    for (int i = 0; i < 4; ++i) {
#pragma unroll
        for (int j = 0; j < 4; ++j) {
            int r = row0 + wm * 64 + i * 16 + (lane >> 2);
            int gcol = n0 + wn * 32 + j * 8 + (lane & 3) * 2;
            float b0 = 0.f, b1 = 0.f;
            if (bias) { b0 = bias[gcol]; b1 = bias[gcol + 1]; }
            if (r < NN) {
                float2 o = make_float2(c[i][j][0] + b0, c[i][j][1] + b1);
                *(float2*)&C[r * ldc + gcol] = o;
            }
            if (r + 8 < NN) {
                float2 o = make_float2(c[i][j][2] + b0, c[i][j][3] + b1);
                *(float2*)&C[(r + 8) * ldc + gcol] = o;
            }
        }
    }
}

// ---------------- GRU gates (torch order r, z, n) ----------------
__global__ void k_gru() {
    int i = blockIdx.x * blockDim.x + threadIdx.x;
    if (i >= NN * HH) return;
    int n = i >> 7, j = i & 127;
    const float* gi = g_gi + n * 384;
    const float* gh = g_gh + n * 384;
    float r = 1.f / (1.f + expf(-(gi[j] + gh[j])));
    float z = 1.f / (1.f + expf(-(gi[128 + j] + gh[128 + j])));
    float nn = tanhf(gi[256 + j] + r * gh[256 + j]);
    float h = g_h[i];
    g_h[i] = (1.f - z) * nn + z * h;
}

// ---------------- classifier + log_softmax ----------------
__global__ void k_cls(const float* __restrict__ lw, const float* __restrict__ lb,
                      float* __restrict__ out) {
    int gt = blockIdx.x * blockDim.x + threadIdx.x;
    int row = gt >> 5;
    int lane = gt & 31;
    if (row >= NN) return;
    const float* hrow = g_h + row * 128;
    float acc[CC];
#pragma unroll
    for (int c = 0; c < CC; ++c) acc[c] = 0.f;
#pragma unroll
    for (int kq = 0; kq < 4; ++kq) {
        int k = lane + kq * 32;
        float hv = hrow[k];
#pragma unroll
        for (int c = 0; c < CC; ++c) acc[c] += hv * lw[c * 128 + k];
    }
#pragma unroll
    for (int c = 0; c < CC; ++c) {
#pragma unroll
        for (int off = 16; off; off >>= 1)
            acc[c] += __shfl_xor_sync(0xffffffffu, acc[c], off);
        acc[c] += lb[c];
    }
    float mx = acc[0];
#pragma unroll
    for (int c = 1; c < CC; ++c) mx = fmaxf(mx, acc[c]);
    float se = 0.f;
#pragma unroll
    for (int c = 0; c < CC; ++c) se += expf(acc[c] - mx);
    float lse = mx + logf(se);
    if (lane < CC) out[row * CC + lane] = acc[lane] - lse;
}

// ---------------- launch ----------------
extern "C" void kernel_launch(void* const* d_in, const int* in_sizes, int n_in,
                              void* d_out, int out_size) {
    const float* x     = (const float*)d_in[0];
    const void*  ei    = d_in[1];
    const float* W     = (const float*)d_in[2];
    const float* w_ih  = (const float*)d_in[3];
    const float* w_hh  = (const float*)d_in[4];
    const float* b_ih  = (const float*)d_in[5];
    const float* b_hh  = (const float*)d_in[6];
    const float* lw    = (const float*)d_in[7];
    const float* lb    = (const float*)d_in[8];
    float* out = (float*)d_out;

    // device-global scratch addresses (query only; no allocation)
    float *p_h, *p_m, *p_agg, *p_gi, *p_gh, *p_Wt;
    cudaGetSymbolAddress((void**)&p_h,   g_h);
    cudaGetSymbolAddress((void**)&p_m,   g_m);
    cudaGetSymbolAddress((void**)&p_agg, g_agg);
    cudaGetSymbolAddress((void**)&p_gi,  g_gi);
    cudaGetSymbolAddress((void**)&p_gh,  g_gh);
    cudaGetSymbolAddress((void**)&p_Wt,  g_Wt);

    // normalize edge index dtype and build CSR
    k_detect<<<1, 32>>>(ei);
    k_convert<<<(2 * EE + 255) / 256, 256>>>(ei);
    k_pad<<<(NN * HH + 255) / 256, 256>>>(x);
    k_transW<<<(LL * HH * HH + 255) / 256, 256>>>(W);
    k_zero_deg<<<(NN + 255) / 256, 256>>>();
    k_hist<<<(EE + 255) / 256, 256>>>();
    k_scan<<<1, 1024>>>();
    k_cursor<<<(NN + 255) / 256, 256>>>();
    k_fill<<<(EE + 255) / 256, 256>>>();

    dim3 gm((NN + 127) / 128, 1);
    dim3 gg((NN + 127) / 128, 3);
    for (int l = 0; l < LL; ++l) {
        k_mma<<<gm, 256>>>(p_h, p_Wt + l * HH * HH, nullptr, p_m, 128);
        k_gather<<<NN, 128>>>();
        k_mma<<<gg, 256>>>(p_agg, w_ih, b_ih, p_gi, 384);
        k_mma<<<gg, 256>>>(p_h, w_hh, b_hh, p_gh, 384);
        k_gru<<<(NN * HH + 255) / 256, 256>>>();
    }
    k_cls<<<(NN * 32 + 255) / 256, 256>>>(lw, lb, out);
}